// round 7
// baseline (speedup 1.0000x reference)
#include <cuda_runtime.h>
#include <cuda_fp16.h>
#include <math.h>
#include <stdint.h>

// ---------------- problem constants ----------------
#define T_TOK    16384
#define D_DIM    2048
#define E_EXP    64
#define TOK_TILE 64
#define NBLK     (T_TOK / TOK_TILE)   // 256
#define KC       32                   // K per chunk
#define NCH      (D_DIM / KC)         // 64

// smem per stage: fp16 tiles, row stride 80B (64B data + 16B pad, conflict-free ldmatrix)
#define RS    80
#define A_HI  0
#define A_LO  5120                    // 64*80
#define B_HI  10240
#define B_LO  15360
#define STG   20480
#define DYN_BYTES (2 * STG)           // 40960

#define PROW 66

__device__ float g_partial[NBLK * E_EXP];
__device__ unsigned int g_cnt = 0;

// ---------------- helpers ----------------
__device__ __forceinline__ uint32_t s2u(const void* p) {
    uint32_t a;
    asm("{ .reg .u64 t; cvta.to.shared.u64 t, %1; cvt.u32.u64 %0, t; }" : "=r"(a) : "l"(p));
    return a;
}

__device__ __forceinline__ void ldsm4(uint32_t* r, uint32_t addr) {
    asm volatile("ldmatrix.sync.aligned.m8n8.x4.shared.b16 {%0,%1,%2,%3}, [%4];"
        : "=r"(r[0]), "=r"(r[1]), "=r"(r[2]), "=r"(r[3]) : "r"(addr));
}

__device__ __forceinline__ void mma16816(float* c, const uint32_t* a, uint32_t b0, uint32_t b1) {
    asm volatile("mma.sync.aligned.m16n8k16.row.col.f32.f16.f16.f32 "
        "{%0,%1,%2,%3}, {%4,%5,%6,%7}, {%8,%9}, {%0,%1,%2,%3};"
        : "+f"(c[0]), "+f"(c[1]), "+f"(c[2]), "+f"(c[3])
        : "r"(a[0]), "r"(a[1]), "r"(a[2]), "r"(a[3]), "r"(b0), "r"(b1));
}

// split one float4 into fp16 hi/lo pairs and store (8B each) to smem
__device__ __forceinline__ void split_sts(float4 v, uint32_t ahi, uint32_t alo) {
    __half2 h0 = __floats2half2_rn(v.x, v.y);
    __half2 h1 = __floats2half2_rn(v.z, v.w);
    float2 f0 = __half22float2(h0);
    float2 f1 = __half22float2(h1);
    __half2 l0 = __floats2half2_rn(v.x - f0.x, v.y - f0.y);
    __half2 l1 = __floats2half2_rn(v.z - f1.x, v.w - f1.y);
    uint32_t u0 = *reinterpret_cast<uint32_t*>(&h0);
    uint32_t u1 = *reinterpret_cast<uint32_t*>(&h1);
    uint32_t w0 = *reinterpret_cast<uint32_t*>(&l0);
    uint32_t w1 = *reinterpret_cast<uint32_t*>(&l1);
    asm volatile("st.shared.v2.u32 [%0], {%1,%2};" :: "r"(ahi), "r"(u0), "r"(u1) : "memory");
    asm volatile("st.shared.v2.u32 [%0], {%1,%2};" :: "r"(alo), "r"(w0), "r"(w1) : "memory");
}

// ---------------- main kernel ----------------
__global__ __launch_bounds__(256, 2)
void router_hmma(const float* __restrict__ x, const float* __restrict__ W,
                 float* __restrict__ out, int out_size)
{
    extern __shared__ __align__(16) char dsm[];
    const uint32_t base = s2u(dsm);

    const int tid  = threadIdx.x;
    const int lane = tid & 31;
    const int wid  = tid >> 5;
    const int wm   = wid & 1;    // m block (32 rows of 64)
    const int wn   = wid >> 1;   // n block (16 cols of 64)
    const int tok_base = blockIdx.x * TOK_TILE;

    // loader assignment: 64 rows x 8 float4 = 512 per matrix, 2 per thread
    int lr[2], lq[2];
#pragma unroll
    for (int j = 0; j < 2; j++) {
        int i = tid + 256 * j;
        lr[j] = i >> 3;
        lq[j] = i & 7;
    }
    const float* gA[2];
    const float* gB[2];
    uint32_t sAd[2], sBd[2];
#pragma unroll
    for (int j = 0; j < 2; j++) {
        gA[j] = x + (size_t)(tok_base + lr[j]) * D_DIM + lq[j] * 4;
        gB[j] = W + (size_t)lr[j] * D_DIM + lq[j] * 4;
        sAd[j] = base + lr[j] * RS + lq[j] * 8;
        sBd[j] = base + lr[j] * RS + lq[j] * 8;
    }

    float4 va[2], vb[2];

    // ldmatrix addresses (stage 0, ks = 0); +ks*32 per kstep, +STG per stage
    uint32_t a_addr[2], b_addr;
#pragma unroll
    for (int mi = 0; mi < 2; mi++) {
        int row = wm * 32 + mi * 16 + (lane & 15);
        int word = lane >> 4;
        a_addr[mi] = base + row * RS + word * 16;
    }
    {
        int row = wn * 16 + (lane & 7) + ((lane & 16) ? 8 : 0);
        int word = (lane >> 3) & 1;
        b_addr = base + row * RS + word * 16;
    }

    float c[2][2][4];
#pragma unroll
    for (int mi = 0; mi < 2; mi++)
#pragma unroll
        for (int nj = 0; nj < 2; nj++)
#pragma unroll
            for (int r = 0; r < 4; r++) c[mi][nj][r] = 0.0f;

    // ---- prologue: chunk0 load+store, chunk1 load ----
#pragma unroll
    for (int j = 0; j < 2; j++) va[j] = *reinterpret_cast<const float4*>(gA[j]);
#pragma unroll
    for (int j = 0; j < 2; j++) vb[j] = *reinterpret_cast<const float4*>(gB[j]);
#pragma unroll
    for (int j = 0; j < 2; j++) split_sts(va[j], sAd[j] + A_HI, sAd[j] + A_LO);
#pragma unroll
    for (int j = 0; j < 2; j++) split_sts(vb[j], sBd[j] + B_HI, sBd[j] + B_LO);
#pragma unroll
    for (int j = 0; j < 2; j++) va[j] = *reinterpret_cast<const float4*>(gA[j] + KC);
#pragma unroll
    for (int j = 0; j < 2; j++) vb[j] = *reinterpret_cast<const float4*>(gB[j] + KC);
    __syncthreads();

    for (int ch = 0; ch < NCH; ch++) {
        const uint32_t sb = (ch & 1) ? STG : 0;

        // 1) all ldmatrix for this chunk (both k-steps)
        uint32_t ah[2][2][4], al[2][2][4], bh[2][4], bl[2][4];
#pragma unroll
        for (int ks = 0; ks < 2; ks++) {
#pragma unroll
            for (int mi = 0; mi < 2; mi++) {
                ldsm4(ah[ks][mi], a_addr[mi] + sb + A_HI + ks * 32);
                ldsm4(al[ks][mi], a_addr[mi] + sb + A_LO + ks * 32);
            }
            ldsm4(bh[ks], b_addr + sb + B_HI + ks * 32);
            ldsm4(bl[ks], b_addr + sb + B_LO + ks * 32);
        }

        // 2) split+store next chunk into other buffer, 3) LDG chunk+2
        if (ch + 1 < NCH) {
            const uint32_t ss = (ch & 1) ? 0 : STG;
#pragma unroll
            for (int j = 0; j < 2; j++) split_sts(va[j], sAd[j] + ss + A_HI, sAd[j] + ss + A_LO);
#pragma unroll
            for (int j = 0; j < 2; j++) split_sts(vb[j], sBd[j] + ss + B_HI, sBd[j] + ss + B_LO);
            if (ch + 2 < NCH) {
                const int k0 = (ch + 2) * KC;
#pragma unroll
                for (int j = 0; j < 2; j++) va[j] = *reinterpret_cast<const float4*>(gA[j] + k0);
#pragma unroll
                for (int j = 0; j < 2; j++) vb[j] = *reinterpret_cast<const float4*>(gB[j] + k0);
            }
        }

        // 4) HMMA consume: nj=0 -> frags 0,1 ; nj=1 -> frags 2,3
#pragma unroll
        for (int ks = 0; ks < 2; ks++) {
#pragma unroll
            for (int mi = 0; mi < 2; mi++)
#pragma unroll
                for (int nj = 0; nj < 2; nj++) {
                    uint32_t b0 = bh[ks][nj * 2], b1 = bh[ks][nj * 2 + 1];
                    uint32_t l0 = bl[ks][nj * 2], l1 = bl[ks][nj * 2 + 1];
                    mma16816(c[mi][nj], ah[ks][mi], b0, b1);  // hh
                    mma16816(c[mi][nj], ah[ks][mi], l0, l1);  // hl
                    mma16816(c[mi][nj], al[ks][mi], b0, b1);  // lh
                }
        }
        __syncthreads();
    }

    // ---------------- epilogue ----------------
    float (*probs)[PROW] = reinterpret_cast<float(*)[PROW]>(dsm);
    float* rZ = reinterpret_cast<float*>(dsm) + TOK_TILE * PROW;

#pragma unroll
    for (int mi = 0; mi < 2; mi++) {
        int r0 = wm * 32 + mi * 16 + (lane >> 2);
#pragma unroll
        for (int nj = 0; nj < 2; nj++) {
            int col = wn * 16 + nj * 8 + (lane & 3) * 2;
            *reinterpret_cast<float2*>(&probs[r0][col])     = make_float2(c[mi][nj][0], c[mi][nj][1]);
            *reinterpret_cast<float2*>(&probs[r0 + 8][col]) = make_float2(c[mi][nj][2], c[mi][nj][3]);
        }
    }
    __syncthreads();

    const int woff = (out_size - 1) / 2;

    if (tid < TOK_TILE) {
        const int t = tid;
        float v1 = -INFINITY, v2 = -INFINITY;
        int i1 = 0, i2 = 0;
#pragma unroll 8
        for (int e = 0; e < E_EXP; e++) {
            float l = probs[t][e];
            if (l > v1)      { v2 = v1; i2 = i1; v1 = l; i1 = e; }
            else if (l > v2) { v2 = l;  i2 = e; }
        }
        float ssum = 0.0f;
#pragma unroll 8
        for (int e = 0; e < E_EXP; e++) {
            float p = expf(probs[t][e] - v1);
            probs[t][e] = p;
            ssum += p;
        }
        rZ[t] = 1.0f / ssum;

        float e2 = expf(v2 - v1);
        float inv = 1.0f / (1.0f + e2);
        int gt = tok_base + t;
        out[2 * gt]            = (float)i1;
        out[2 * gt + 1]        = (float)i2;
        out[woff + 2 * gt]     = inv;
        out[woff + 2 * gt + 1] = e2 * inv;
    }
    __syncthreads();

    if (tid < E_EXP) {
        float u = 0.0f;
#pragma unroll 8
        for (int t = 0; t < TOK_TILE; t++)
            u += probs[t][tid] * rZ[t];
        g_partial[blockIdx.x * E_EXP + tid] = u;
    }

    // ---------------- fused aux-loss reduction (last block) ----------------
    __threadfence();
    __syncthreads();
    __shared__ unsigned int s_last;
    if (tid == 0) s_last = (atomicAdd(&g_cnt, 1u) == (unsigned)(NBLK - 1));
    __syncthreads();
    if (s_last) {
        __threadfence();
        float (*red)[E_EXP] = reinterpret_cast<float(*)[E_EXP]>(dsm);
        float* sq = reinterpret_cast<float*>(dsm) + 4 * E_EXP;
        const int e = tid & 63;
        const int part = tid >> 6;  // 0..3, 64 blocks each
        float u = 0.0f;
#pragma unroll 8
        for (int b = part * 64; b < part * 64 + 64; b++)
            u += g_partial[b * E_EXP + e];
        red[part][e] = u;
        __syncthreads();
        if (tid < E_EXP) {
            float s = (red[0][tid] + red[1][tid]) + (red[2][tid] + red[3][tid]);
            s *= (1.0f / (float)T_TOK);
            float d = s - 1.0f / (float)E_EXP;
            sq[tid] = d * d;
        }
        __syncthreads();
        if (tid < 32) {
            float s = sq[tid] + sq[tid + 32];
#pragma unroll
            for (int o = 16; o > 0; o >>= 1)
                s += __shfl_down_sync(0xFFFFFFFFu, s, o);
            if (tid == 0) {
                out[out_size - 1] = s;
                g_cnt = 0;  // reset for next graph replay
            }
        }
    }
}

extern "C" void kernel_launch(void* const* d_in, const int* in_sizes, int n_in,
                              void* d_out, int out_size)
{
    const float* x = (const float*)d_in[0];
    const float* W = (const float*)d_in[1];
    float* out = (float*)d_out;

    cudaFuncSetAttribute(router_hmma, cudaFuncAttributeMaxDynamicSharedMemorySize, DYN_BYTES);
    router_hmma<<<NBLK, 256, DYN_BYTES>>>(x, W, out, out_size);
}